// round 5
// baseline (speedup 1.0000x reference)
#include <cuda_runtime.h>
#include <cstdint>
#include <cstddef>

#define NNODES   50000
#define EDGESMAX 800000
#define HDIM     256   // NUM_HEADS * OUT_DIM

// -------- scratch (static __device__ arrays; no allocation allowed) --------
__device__ float g_Q[(size_t)NNODES * HDIM];
__device__ float g_K[(size_t)NNODES * HDIM];
__device__ float g_V[(size_t)NNODES * HDIM];
__device__ int   g_deg[NNODES];
__device__ int   g_cursor[NNODES];
__device__ int   g_rowptr[NNODES + 1];
__device__ int   g_csr_src[EDGESMAX];

__device__ __forceinline__ uint32_t f2tf32(float x) {
    uint32_t r;
    asm("cvt.rna.tf32.f32 %0, %1;" : "=r"(r) : "f"(x));
    return r;
}

// ---------------------------------------------------------------------------
// CSR build: zero deg -> histogram -> exclusive scan (seeds cursor) -> scatter
// ---------------------------------------------------------------------------
__global__ void zero_deg(int n_nodes) {
    int i = blockIdx.x * blockDim.x + threadIdx.x;
    if (i < n_nodes) g_deg[i] = 0;
}

__global__ void hist_kernel(const int* __restrict__ dst, int E) {
    int e = blockIdx.x * blockDim.x + threadIdx.x;
    if (e < E) atomicAdd(&g_deg[dst[e]], 1);
}

__global__ __launch_bounds__(1024) void scan_kernel(int n) {
    __shared__ int warp_sums[32];
    __shared__ int s_carry;
    const int tid  = threadIdx.x;
    const int lane = tid & 31;
    const int wid  = tid >> 5;
    if (tid == 0) s_carry = 0;
    __syncthreads();

    for (int base = 0; base < n; base += 1024) {
        int i = base + tid;
        int v = (i < n) ? g_deg[i] : 0;
        int x = v;
        #pragma unroll
        for (int off = 1; off < 32; off <<= 1) {
            int t = __shfl_up_sync(0xffffffffu, x, off);
            if (lane >= off) x += t;
        }
        if (lane == 31) warp_sums[wid] = x;
        __syncthreads();
        if (wid == 0) {
            int w = warp_sums[lane];
            #pragma unroll
            for (int off = 1; off < 32; off <<= 1) {
                int t = __shfl_up_sync(0xffffffffu, w, off);
                if (lane >= off) w += t;
            }
            warp_sums[lane] = w;
        }
        __syncthreads();
        int warp_off = (wid > 0) ? warp_sums[wid - 1] : 0;
        int excl = s_carry + x + warp_off - v;
        if (i < n) { g_rowptr[i] = excl; g_cursor[i] = excl; }
        __syncthreads();
        if (tid == 1023) s_carry += warp_sums[31];
        __syncthreads();
    }
    if (tid == 0) g_rowptr[n] = s_carry;
}

__global__ void scatter_kernel(const int* __restrict__ src,
                               const int* __restrict__ dst, int E) {
    int e = blockIdx.x * blockDim.x + threadIdx.x;
    if (e < E) {
        int pos = atomicAdd(&g_cursor[dst[e]], 1);
        g_csr_src[pos] = src[e];
    }
}

// ---------------------------------------------------------------------------
// Kernel 1: fused QKV projection.  TF32 mma m16n8k8, tile 128x128x32.
// ---------------------------------------------------------------------------
__global__ __launch_bounds__(256) void qkv_gemm(
    const float* __restrict__ h,
    const float* __restrict__ Wq, const float* __restrict__ bq,
    const float* __restrict__ Wk, const float* __restrict__ bk,
    const float* __restrict__ Wv, const float* __restrict__ bv,
    int Nrows)
{
    __shared__ uint32_t As[128 * 36];
    __shared__ uint32_t Bs[128 * 36];

    const int tid  = threadIdx.x;
    const int lane = tid & 31;
    const int warp = tid >> 5;
    const int wm = warp >> 2;
    const int wn = warp & 3;
    const int bm = blockIdx.x;
    const int bn = blockIdx.y;

    const float* W;  const float* bias;  float* target;
    if (bn < 2)      { W = Wq; bias = bq; target = g_Q; }
    else if (bn < 4) { W = Wk; bias = bk; target = g_K; }
    else             { W = Wv; bias = bv; target = g_V; }
    const int ncol0 = (bn & 1) * 128;

    float acc[4][4][4];
    #pragma unroll
    for (int i = 0; i < 4; i++)
        #pragma unroll
        for (int j = 0; j < 4; j++)
            #pragma unroll
            for (int k = 0; k < 4; k++) acc[i][j][k] = 0.0f;

    const int lr = tid >> 3;
    const int lc = (tid & 7) * 4;

    for (int kb = 0; kb < 256; kb += 32) {
        #pragma unroll
        for (int i = 0; i < 4; i++) {
            int r = lr + i * 32;
            int grow = bm * 128 + r;
            float4 v = make_float4(0.f, 0.f, 0.f, 0.f);
            if (grow < Nrows)
                v = *(const float4*)(h + (size_t)grow * 256 + kb + lc);
            uint32_t* s = &As[r * 36 + lc];
            s[0] = f2tf32(v.x); s[1] = f2tf32(v.y);
            s[2] = f2tf32(v.z); s[3] = f2tf32(v.w);
        }
        #pragma unroll
        for (int i = 0; i < 4; i++) {
            int r = lr + i * 32;
            float4 v = *(const float4*)(W + (size_t)(ncol0 + r) * 256 + kb + lc);
            uint32_t* s = &Bs[r * 36 + lc];
            s[0] = f2tf32(v.x); s[1] = f2tf32(v.y);
            s[2] = f2tf32(v.z); s[3] = f2tf32(v.w);
        }
        __syncthreads();

        #pragma unroll
        for (int ks = 0; ks < 4; ks++) {
            const int k0 = ks * 8;
            uint32_t a[4][4], b[4][2];
            #pragma unroll
            for (int mt = 0; mt < 4; mt++) {
                int r = wm * 64 + mt * 16 + (lane >> 2);
                int c = k0 + (lane & 3);
                a[mt][0] = As[r * 36 + c];
                a[mt][1] = As[(r + 8) * 36 + c];
                a[mt][2] = As[r * 36 + c + 4];
                a[mt][3] = As[(r + 8) * 36 + c + 4];
            }
            #pragma unroll
            for (int nt = 0; nt < 4; nt++) {
                int n = wn * 32 + nt * 8 + (lane >> 2);
                int c = k0 + (lane & 3);
                b[nt][0] = Bs[n * 36 + c];
                b[nt][1] = Bs[n * 36 + c + 4];
            }
            #pragma unroll
            for (int mt = 0; mt < 4; mt++)
                #pragma unroll
                for (int nt = 0; nt < 4; nt++)
                    asm volatile(
                        "mma.sync.aligned.m16n8k8.row.col.f32.tf32.tf32.f32 "
                        "{%0,%1,%2,%3}, {%4,%5,%6,%7}, {%8,%9}, {%0,%1,%2,%3};"
                        : "+f"(acc[mt][nt][0]), "+f"(acc[mt][nt][1]),
                          "+f"(acc[mt][nt][2]), "+f"(acc[mt][nt][3])
                        : "r"(a[mt][0]), "r"(a[mt][1]), "r"(a[mt][2]), "r"(a[mt][3]),
                          "r"(b[nt][0]), "r"(b[nt][1]));
        }
        __syncthreads();
    }

    #pragma unroll
    for (int mt = 0; mt < 4; mt++) {
        int r0 = wm * 64 + mt * 16 + (lane >> 2);
        #pragma unroll
        for (int nt = 0; nt < 4; nt++) {
            int c0 = wn * 32 + nt * 8 + (lane & 3) * 2;
            #pragma unroll
            for (int cc = 0; cc < 4; cc++) {
                int r = r0 + ((cc >= 2) ? 8 : 0);
                int c = c0 + (cc & 1);
                int grow = bm * 128 + r;
                if (grow < Nrows) {
                    int j = ncol0 + c;
                    target[(size_t)grow * 256 + j] = acc[mt][nt][cc] + bias[j];
                }
            }
        }
    }
}

// ---------------------------------------------------------------------------
// Kernel 2: single-pass fused attention, latency-optimized.
// One warp per destination node. Edge indices are prefetched 32 at a time
// (one coalesced load per lane, then register shuffles). The edge loop is
// manually unrolled 4-wide: 16 independent float4 LDGs issue before any
// consumption, lifting MLP ~4 -> ~16. Invalid (tail) slots load a clamped
// valid index and get their score masked to zero.
// ---------------------------------------------------------------------------
__global__ __launch_bounds__(256) void attn_fused(
    float* __restrict__ out, int n_nodes)
{
    const int node = (blockIdx.x * blockDim.x + threadIdx.x) >> 5;
    if (node >= n_nodes) return;
    const int lane = threadIdx.x & 31;
    const unsigned FULL = 0xffffffffu;
    const float inv = 0.17677669529663687f;   // 1/sqrt(32)

    const int beg = g_rowptr[node];
    const int end = g_rowptr[node + 1];

    const float4* Qr = (const float4*)(g_Q + (size_t)node * 256);
    const float4 q0 = Qr[lane];
    const float4 q1 = Qr[lane + 32];

    float4 acc0 = make_float4(0.f, 0.f, 0.f, 0.f);
    float4 acc1 = make_float4(0.f, 0.f, 0.f, 0.f);
    float z0 = 0.0f, z1 = 0.0f;

    for (int base = beg; base < end; base += 32) {
        const int cnt = min(32, end - base);
        // coalesced index prefetch: lane j holds edge base+j's src
        int my_src = g_csr_src[base + min(lane, cnt - 1)];

        for (int j = 0; j < cnt; j += 4) {
            // resolve 4 indices from registers (clamped for tail)
            int s0 = __shfl_sync(FULL, my_src, j);
            int s1 = __shfl_sync(FULL, my_src, min(j + 1, cnt - 1));
            int s2 = __shfl_sync(FULL, my_src, min(j + 2, cnt - 1));
            int s3 = __shfl_sync(FULL, my_src, min(j + 3, cnt - 1));

            const float4* K0 = (const float4*)(g_K + (size_t)s0 * 256);
            const float4* K1 = (const float4*)(g_K + (size_t)s1 * 256);
            const float4* K2 = (const float4*)(g_K + (size_t)s2 * 256);
            const float4* K3 = (const float4*)(g_K + (size_t)s3 * 256);
            const float4* V0 = (const float4*)(g_V + (size_t)s0 * 256);
            const float4* V1 = (const float4*)(g_V + (size_t)s1 * 256);
            const float4* V2 = (const float4*)(g_V + (size_t)s2 * 256);
            const float4* V3 = (const float4*)(g_V + (size_t)s3 * 256);

            // issue ALL loads before consuming any (max MLP)
            float4 ka0 = K0[lane], kb0 = K0[lane + 32];
            float4 ka1 = K1[lane], kb1 = K1[lane + 32];
            float4 ka2 = K2[lane], kb2 = K2[lane + 32];
            float4 ka3 = K3[lane], kb3 = K3[lane + 32];
            float4 va0 = V0[lane], vb0 = V0[lane + 32];
            float4 va1 = V1[lane], vb1 = V1[lane + 32];
            float4 va2 = V2[lane], vb2 = V2[lane + 32];
            float4 va3 = V3[lane], vb3 = V3[lane + 32];

            // partial dots
            float p00 = ka0.x*q0.x + ka0.y*q0.y + ka0.z*q0.z + ka0.w*q0.w;
            float p10 = kb0.x*q1.x + kb0.y*q1.y + kb0.z*q1.z + kb0.w*q1.w;
            float p01 = ka1.x*q0.x + ka1.y*q0.y + ka1.z*q0.z + ka1.w*q0.w;
            float p11 = kb1.x*q1.x + kb1.y*q1.y + kb1.z*q1.z + kb1.w*q1.w;
            float p02 = ka2.x*q0.x + ka2.y*q0.y + ka2.z*q0.z + ka2.w*q0.w;
            float p12 = kb2.x*q1.x + kb2.y*q1.y + kb2.z*q1.z + kb2.w*q1.w;
            float p03 = ka3.x*q0.x + ka3.y*q0.y + ka3.z*q0.z + ka3.w*q0.w;
            float p13 = kb3.x*q1.x + kb3.y*q1.y + kb3.z*q1.z + kb3.w*q1.w;

            #pragma unroll
            for (int off = 4; off; off >>= 1) {
                p00 += __shfl_xor_sync(FULL, p00, off);
                p10 += __shfl_xor_sync(FULL, p10, off);
                p01 += __shfl_xor_sync(FULL, p01, off);
                p11 += __shfl_xor_sync(FULL, p11, off);
                p02 += __shfl_xor_sync(FULL, p02, off);
                p12 += __shfl_xor_sync(FULL, p12, off);
                p03 += __shfl_xor_sync(FULL, p03, off);
                p13 += __shfl_xor_sync(FULL, p13, off);
            }

            float m1 = (j + 1 < cnt) ? 1.0f : 0.0f;
            float m2 = (j + 2 < cnt) ? 1.0f : 0.0f;
            float m3 = (j + 3 < cnt) ? 1.0f : 0.0f;

            float sc00 =      __expf(fminf(fmaxf(p00 * inv, -5.0f), 5.0f));
            float sc10 =      __expf(fminf(fmaxf(p10 * inv, -5.0f), 5.0f));
            float sc01 = m1 * __expf(fminf(fmaxf(p01 * inv, -5.0f), 5.0f));
            float sc11 = m1 * __expf(fminf(fmaxf(p11 * inv, -5.0f), 5.0f));
            float sc02 = m2 * __expf(fminf(fmaxf(p02 * inv, -5.0f), 5.0f));
            float sc12 = m2 * __expf(fminf(fmaxf(p12 * inv, -5.0f), 5.0f));
            float sc03 = m3 * __expf(fminf(fmaxf(p03 * inv, -5.0f), 5.0f));
            float sc13 = m3 * __expf(fminf(fmaxf(p13 * inv, -5.0f), 5.0f));

            z0 += sc00 + sc01 + sc02 + sc03;
            z1 += sc10 + sc11 + sc12 + sc13;

            acc0.x += sc00*va0.x + sc01*va1.x + sc02*va2.x + sc03*va3.x;
            acc0.y += sc00*va0.y + sc01*va1.y + sc02*va2.y + sc03*va3.y;
            acc0.z += sc00*va0.z + sc01*va1.z + sc02*va2.z + sc03*va3.z;
            acc0.w += sc00*va0.w + sc01*va1.w + sc02*va2.w + sc03*va3.w;
            acc1.x += sc10*vb0.x + sc11*vb1.x + sc12*vb2.x + sc13*vb3.x;
            acc1.y += sc10*vb0.y + sc11*vb1.y + sc12*vb2.y + sc13*vb3.y;
            acc1.z += sc10*vb0.z + sc11*vb1.z + sc12*vb2.z + sc13*vb3.z;
            acc1.w += sc10*vb0.w + sc11*vb1.w + sc12*vb2.w + sc13*vb3.w;
        }
    }

    const float rz0 = (z0 > 0.0f) ? 1.0f / z0 : 0.0f;
    const float rz1 = (z1 > 0.0f) ? 1.0f / z1 : 0.0f;
    acc0.x *= rz0; acc0.y *= rz0; acc0.z *= rz0; acc0.w *= rz0;
    acc1.x *= rz1; acc1.y *= rz1; acc1.z *= rz1; acc1.w *= rz1;

    float4* o = (float4*)(out + (size_t)node * 256);
    o[lane]      = acc0;
    o[lane + 32] = acc1;
}

// ---------------------------------------------------------------------------
extern "C" void kernel_launch(void* const* d_in, const int* in_sizes, int n_in,
                              void* d_out, int out_size)
{
    const float* h  = (const float*)d_in[0];
    const float* Wq = (const float*)d_in[1];
    const float* bq = (const float*)d_in[2];
    const float* Wk = (const float*)d_in[3];
    const float* bk = (const float*)d_in[4];
    const float* Wv = (const float*)d_in[5];
    const float* bv = (const float*)d_in[6];
    const int*   src = (const int*)d_in[7];
    const int*   dst = (const int*)d_in[8];
    float* out = (float*)d_out;

    const int N = in_sizes[0] / 256;   // 50000
    const int E = in_sizes[7];         // 800000

    zero_deg<<<(N + 255) / 256, 256>>>(N);
    hist_kernel<<<(E + 255) / 256, 256>>>(dst, E);
    scan_kernel<<<1, 1024>>>(N);
    scatter_kernel<<<(E + 255) / 256, 256>>>(src, dst, E);

    dim3 grid((N + 127) / 128, 6);
    qkv_gemm<<<grid, 256>>>(h, Wq, bq, Wk, bk, Wv, bv, N);

    attn_fused<<<(N * 32 + 255) / 256, 256>>>(out, N);
}